// round 1
// baseline (speedup 1.0000x reference)
#include <cuda_runtime.h>
#include <cuda_bf16.h>
#include <math.h>
#include <stdint.h>

#define E 8
#define KTOP 2
#define DM 1024
#define HID 4096
#define MAXN 16384
#define MAXM (MAXN*KTOP)

#define BM 128
#define BN 128
#define BK 32
#define BKP 40          // padded k-stride (bf16 elems) -> conflict-free frag loads
#define MTILES 20
#define CAPP (MTILES*BM)   // 2560 padded capacity rows per expert

// ---------------- device scratch (static: no allocations allowed) ----------
__device__ int   g_cnt[E];
__device__ int   g_bm[E*MAXM];      // flat assignment index m = tok*2+slot
__device__ float g_bg[E*MAXM];      // gate
__device__ int   g_disp_tok[E*CAPP];
__device__ float g_disp_g[E*CAPP];
__device__ int   g_kept[E];
__device__ float g_h[(size_t)E*CAPP*HID];   // expert hidden activations (fp32)

// ---------------- small kernels --------------------------------------------
__global__ void zero_cnt_kernel() {
    if (threadIdx.x < E) g_cnt[threadIdx.x] = 0;
}

// One warp per token: logits = x@Wr + br, softmax, top-2 (stable ties),
// push (m, gate) into per-expert buckets.
__global__ void router_kernel(const float* __restrict__ x,
                              const float* __restrict__ Wr,
                              const float* __restrict__ br, int N) {
    __shared__ float sWr[DM*E];
    for (int i = threadIdx.x; i < DM*E; i += blockDim.x) sWr[i] = Wr[i];
    __syncthreads();
    int warp = threadIdx.x >> 5, lane = threadIdx.x & 31;
    int tok = blockIdx.x * 8 + warp;
    if (tok >= N) return;
    const float* xr = x + (size_t)tok * DM;
    float acc[E];
#pragma unroll
    for (int e = 0; e < E; e++) acc[e] = 0.f;
    for (int d = lane; d < DM; d += 32) {
        float xv = xr[d];
#pragma unroll
        for (int e = 0; e < E; e++) acc[e] += xv * sWr[d*E + e];
    }
#pragma unroll
    for (int e = 0; e < E; e++) {
#pragma unroll
        for (int o = 16; o > 0; o >>= 1) acc[e] += __shfl_xor_sync(0xffffffffu, acc[e], o);
    }
    if (lane == 0) {
        float l[E]; float mx = -1e30f;
#pragma unroll
        for (int e = 0; e < E; e++) { l[e] = acc[e] + br[e]; mx = fmaxf(mx, l[e]); }
        float s = 0.f;
#pragma unroll
        for (int e = 0; e < E; e++) { l[e] = expf(l[e] - mx); s += l[e]; }
        int i1 = 0; float p1 = -1.f;
#pragma unroll
        for (int e = 0; e < E; e++) { if (l[e] > p1) { p1 = l[e]; i1 = e; } }
        int i2 = -1; float p2 = -1.f;
#pragma unroll
        for (int e = 0; e < E; e++) { if (e != i1 && l[e] > p2) { p2 = l[e]; i2 = e; } }
        float inv = 1.f / s;
        int m0 = tok * 2;
        int pos = atomicAdd(&g_cnt[i1], 1);
        g_bm[i1*MAXM + pos] = m0;     g_bg[i1*MAXM + pos] = p1 * inv;
        pos = atomicAdd(&g_cnt[i2], 1);
        g_bm[i2*MAXM + pos] = m0 + 1; g_bg[i2*MAXM + pos] = p2 * inv;
    }
}

// Exact rank within expert by (gate desc, flat index asc) == reference lexsort.
#define RCH 1024
__global__ void rank_kernel(int cap) {
    __shared__ float sg[RCH];
    __shared__ int   sm[RCH];
    int e = blockIdx.y;
    int cnt = g_cnt[e];
    if (blockIdx.x == 0 && threadIdx.x == 0) g_kept[e] = min(cnt, cap);
    int i = blockIdx.x * blockDim.x + threadIdx.x;
    bool has = (i < cnt);
    float gi = has ? g_bg[e*MAXM + i] : 0.f;
    int   mi = has ? g_bm[e*MAXM + i] : 0;
    int rank = 0;
    for (int j0 = 0; j0 < cnt; j0 += RCH) {
        int nj = min(RCH, cnt - j0);
        __syncthreads();
        for (int j = threadIdx.x; j < nj; j += blockDim.x) {
            sg[j] = g_bg[e*MAXM + j0 + j];
            sm[j] = g_bm[e*MAXM + j0 + j];
        }
        __syncthreads();
        if (has) {
            for (int j = 0; j < nj; j++) {
                float gj = sg[j]; int mj = sm[j];
                rank += (gj > gi) || (gj == gi && mj < mi);
            }
        }
    }
    if (has && rank < cap) {
        g_disp_tok[e*CAPP + rank] = mi >> 1;
        g_disp_g[e*CAPP + rank]   = gi;
    }
}

// ---------------- GEMM machinery -------------------------------------------
__device__ __forceinline__ void mma16816(float& d0, float& d1, float& d2, float& d3,
                                         uint32_t a0, uint32_t a1, uint32_t a2, uint32_t a3,
                                         uint32_t b0, uint32_t b1) {
    asm volatile("mma.sync.aligned.m16n8k16.row.col.f32.bf16.bf16.f32 "
                 "{%0,%1,%2,%3}, {%4,%5,%6,%7}, {%8,%9}, {%0,%1,%2,%3};\n"
                 : "+f"(d0), "+f"(d1), "+f"(d2), "+f"(d3)
                 : "r"(a0), "r"(a1), "r"(a2), "r"(a3), "r"(b0), "r"(b1));
}

__device__ __forceinline__ float silu_f(float z) {
    return z / (1.f + expf(-z));
}

// One kernel for both GEMMs.
// IS2==0: A = gathered x rows [capp, DM], B = W1[e] [DM,HID], epi: silu(+b1) -> g_h
// IS2==1: A = g_h rows [capp, HID], B = W2[e] [HID,DM], epi: (+b2)*gate -> atomicAdd y
template <int KDIM, int NDIM, int IS2>
__global__ __launch_bounds__(256, 1)
void ffn_gemm_kernel(const float* __restrict__ X,
                     const float* __restrict__ W,
                     const float* __restrict__ Bias,
                     float* __restrict__ Y) {
    __shared__ __nv_bfloat16 As[2][BM][BKP];
    __shared__ __nv_bfloat16 Bs[2][BN][BKP];
    __shared__ int   stok[BM];
    __shared__ float sgate[BM];

    const int tid = threadIdx.x;
    const int e  = blockIdx.z;
    const int m0 = blockIdx.y * BM;
    const int n0 = blockIdx.x * BN;
    const int kept = g_kept[e];

    if (tid < BM) {
        int r = m0 + tid;
        bool v = r < kept;
        stok[tid]  = v ? g_disp_tok[e*CAPP + r] : 0;
        sgate[tid] = v ? g_disp_g[e*CAPP + r]   : 0.f;
    }
    __syncthreads();

    const int warp = tid >> 5, lane = tid & 31;
    const int wm = (warp >> 2) * 64;   // 2 warps along M
    const int wn = (warp & 3) * 32;    // 4 warps along N
    const int gp = lane >> 2, tg = lane & 3;

    float D[4][4][4];
#pragma unroll
    for (int a = 0; a < 4; a++)
#pragma unroll
        for (int b = 0; b < 4; b++)
#pragma unroll
            for (int c = 0; c < 4; c++) D[a][b][c] = 0.f;

    // staging registers
    float4 aS[4], bS[4];
    const int ar  = tid >> 1;
    const int akh = (tid & 1) * 16;
    const int bkr = tid >> 5;
    const int bnn = (tid & 31) * 4;
    const bool a_valid = IS2 ? true : ((m0 + ar) < kept);

    const int ktiles = KDIM / BK;

#define LOAD_TILE(KT)                                                          \
    do {                                                                       \
        int k0 = (KT) * BK;                                                    \
        const float* ap;                                                       \
        if (IS2) ap = g_h + ((size_t)(e*CAPP + m0 + ar))*HID + k0 + akh;       \
        else     ap = X + (size_t)stok[ar]*DM + k0 + akh;                      \
        _Pragma("unroll")                                                      \
        for (int j = 0; j < 4; j++)                                            \
            aS[j] = a_valid ? __ldg((const float4*)(ap + 4*j))                 \
                            : make_float4(0.f,0.f,0.f,0.f);                    \
        const float* bp = W + (size_t)e*KDIM*NDIM + (size_t)(k0 + bkr)*NDIM    \
                          + n0 + bnn;                                          \
        _Pragma("unroll")                                                      \
        for (int p = 0; p < 4; p++)                                            \
            bS[p] = __ldg((const float4*)(bp + (size_t)p*8*NDIM));             \
    } while (0)

#define STORE_TILE()                                                           \
    do {                                                                       \
        _Pragma("unroll")                                                      \
        for (int j = 0; j < 4; j++) {                                          \
            float v0 = aS[j].x, v1 = aS[j].y, v2 = aS[j].z, v3 = aS[j].w;      \
            __nv_bfloat16 h0 = __float2bfloat16(v0), h1 = __float2bfloat16(v1);\
            __nv_bfloat16 h2 = __float2bfloat16(v2), h3 = __float2bfloat16(v3);\
            __nv_bfloat16 l0 = __float2bfloat16(v0 - __bfloat162float(h0));    \
            __nv_bfloat16 l1 = __float2bfloat16(v1 - __bfloat162float(h1));    \
            __nv_bfloat16 l2 = __float2bfloat16(v2 - __bfloat162float(h2));    \
            __nv_bfloat16 l3 = __float2bfloat16(v3 - __bfloat162float(h3));    \
            *(__nv_bfloat162*)&As[0][ar][akh + j*4]     = __halves2bfloat162(h0,h1);\
            *(__nv_bfloat162*)&As[0][ar][akh + j*4 + 2] = __halves2bfloat162(h2,h3);\
            *(__nv_bfloat162*)&As[1][ar][akh + j*4]     = __halves2bfloat162(l0,l1);\
            *(__nv_bfloat162*)&As[1][ar][akh + j*4 + 2] = __halves2bfloat162(l2,l3);\
        }                                                                      \
        _Pragma("unroll")                                                      \
        for (int p = 0; p < 4; p++) {                                          \
            int k = p*8 + bkr;                                                 \
            float vv[4] = {bS[p].x, bS[p].y, bS[p].z, bS[p].w};                \
            _Pragma("unroll")                                                  \
            for (int c = 0; c < 4; c++) {                                      \
                __nv_bfloat16 hi = __float2bfloat16(vv[c]);                    \
                __nv_bfloat16 lo = __float2bfloat16(vv[c] - __bfloat162float(hi));\
                Bs[0][bnn + c][k] = hi;                                        \
                Bs[1][bnn + c][k] = lo;                                        \
            }                                                                  \
        }                                                                      \
    } while (0)

    LOAD_TILE(0);
    STORE_TILE();
    __syncthreads();

    for (int kt = 0; kt < ktiles; kt++) {
        if (kt + 1 < ktiles) LOAD_TILE(kt + 1);

#pragma unroll
        for (int kk = 0; kk < BK; kk += 16) {
            uint32_t Ah[4][4], Al[4][4], Bh[4][2], Bl[4][2];
#pragma unroll
            for (int mt = 0; mt < 4; mt++) {
                int row = wm + mt*16 + gp;
                Ah[mt][0] = *(const uint32_t*)&As[0][row  ][kk + 2*tg];
                Ah[mt][1] = *(const uint32_t*)&As[0][row+8][kk + 2*tg];
                Ah[mt][2] = *(const uint32_t*)&As[0][row  ][kk + 2*tg + 8];
                Ah[mt][3] = *(const uint32_t*)&As[0][row+8][kk + 2*tg + 8];
                Al[mt][0] = *(const uint32_t*)&As[1][row  ][kk + 2*tg];
                Al[mt][1] = *(const uint32_t*)&As[1][row+8][kk + 2*tg];
                Al[mt][2] = *(const uint32_t*)&As[1][row  ][kk + 2*tg + 8];
                Al[mt][3] = *(const uint32_t*)&As[1][row+8][kk + 2*tg + 8];
            }
#pragma unroll
            for (int nt = 0; nt < 4; nt++) {
                int col = wn + nt*8 + gp;
                Bh[nt][0] = *(const uint32_t*)&Bs[0][col][kk + 2*tg];
                Bh[nt][1] = *(const uint32_t*)&Bs[0][col][kk + 2*tg + 8];
                Bl[nt][0] = *(const uint32_t*)&Bs[1][col][kk + 2*tg];
                Bl[nt][1] = *(const uint32_t*)&Bs[1][col][kk + 2*tg + 8];
            }
#pragma unroll
            for (int mt = 0; mt < 4; mt++)
#pragma unroll
                for (int nt = 0; nt < 4; nt++) {
                    mma16816(D[mt][nt][0], D[mt][nt][1], D[mt][nt][2], D[mt][nt][3],
                             Ah[mt][0], Ah[mt][1], Ah[mt][2], Ah[mt][3],
                             Bh[nt][0], Bh[nt][1]);
                    mma16816(D[mt][nt][0], D[mt][nt][1], D[mt][nt][2], D[mt][nt][3],
                             Ah[mt][0], Ah[mt][1], Ah[mt][2], Ah[mt][3],
                             Bl[nt][0], Bl[nt][1]);
                    mma16816(D[mt][nt][0], D[mt][nt][1], D[mt][nt][2], D[mt][nt][3],
                             Al[mt][0], Al[mt][1], Al[mt][2], Al[mt][3],
                             Bh[nt][0], Bh[nt][1]);
                }
        }
        __syncthreads();
        if (kt + 1 < ktiles) {
            STORE_TILE();
            __syncthreads();
        }
    }

    // epilogue
#pragma unroll
    for (int mt = 0; mt < 4; mt++) {
#pragma unroll
        for (int nt = 0; nt < 4; nt++) {
            int lr = wm + mt*16 + gp;
            int c  = wn + nt*8 + 2*tg;
            int gn = n0 + c;
            float2 bb = *(const float2*)&Bias[(size_t)e*NDIM + gn];
#pragma unroll
            for (int half = 0; half < 2; half++) {
                int lrow = lr + half*8;
                int r = m0 + lrow;
                float v0 = D[mt][nt][half*2 + 0];
                float v1 = D[mt][nt][half*2 + 1];
                if (!IS2) {
                    bool val = r < kept;
                    float o0 = val ? silu_f(v0 + bb.x) : 0.f;
                    float o1 = val ? silu_f(v1 + bb.y) : 0.f;
                    float2 o = make_float2(o0, o1);
                    *(float2*)&g_h[((size_t)(e*CAPP + r))*HID + gn] = o;
                } else {
                    if (r < kept) {
                        int tok = stok[lrow];
                        float g = sgate[lrow];
                        atomicAdd(&Y[(size_t)tok*DM + gn    ], (v0 + bb.x) * g);
                        atomicAdd(&Y[(size_t)tok*DM + gn + 1], (v1 + bb.y) * g);
                    }
                }
            }
        }
    }
#undef LOAD_TILE
#undef STORE_TILE
}

// ---------------- launch ----------------------------------------------------
extern "C" void kernel_launch(void* const* d_in, const int* in_sizes, int n_in,
                              void* d_out, int out_size) {
    const float* x  = (const float*)d_in[0];
    const float* Wr = (const float*)d_in[1];
    const float* br = (const float*)d_in[2];
    const float* W1 = (const float*)d_in[3];
    const float* b1 = (const float*)d_in[4];
    const float* W2 = (const float*)d_in[5];
    const float* b2 = (const float*)d_in[6];
    float* y = (float*)d_out;

    int N = in_sizes[0] / DM;
    if (N > MAXN) N = MAXN;
    int cap = (int)ceil(1.2 * (double)N / (double)E);
    if (cap > CAPP) cap = CAPP;
    int mt = (cap + BM - 1) / BM;

    cudaMemsetAsync(y, 0, (size_t)N * DM * sizeof(float));
    zero_cnt_kernel<<<1, 32>>>();
    router_kernel<<<(N + 7) / 8, 256>>>(x, Wr, br, N);

    dim3 rg((KTOP * N + 255) / 256, E);
    rank_kernel<<<rg, 256>>>(cap);

    dim3 g1(HID / BN, mt, E);
    ffn_gemm_kernel<DM, HID, 0><<<g1, 256>>>(x, W1, b1, y);

    dim3 g2(DM / BN, mt, E);
    ffn_gemm_kernel<HID, DM, 1><<<g2, 256>>>(x, W2, b2, y);
}

// round 3
// speedup vs baseline: 2.6310x; 2.6310x over previous
#include <cuda_runtime.h>
#include <math.h>
#include <stdint.h>

#define E 8
#define DM 1024
#define HID 4096
#define MAXN 16384
#define MAXM (MAXN*2)

#define BM 128
#define BN 128
#define BK 32
#define MTILES 20
#define CAPP (MTILES*BM)     // 2560 padded capacity rows per expert

// smem layout (bytes), per stage
#define A_STRIDE 80          // 40 bf16 per A row (128 rows)
#define B_STRIDE 272         // 136 bf16 per B k-row (32 rows)
#define OFF_AHI 0
#define OFF_ALO 10240
#define OFF_BHI 20480
#define OFF_BLO 29184
#define STAGE   38912
#define SMEM_TOTAL (2*STAGE + 1024)

// ---------------- device scratch ----------------
__device__ int   g_cnt[E];
__device__ int   g_bm[E*MAXM];
__device__ float g_bg[E*MAXM];
__device__ int   g_disp_tok[E*CAPP];
__device__ float g_disp_g[E*CAPP];
__device__ int   g_kept[E];
__device__ float g_h[(size_t)E*CAPP*HID];

// ---------------- helpers ----------------
__device__ __forceinline__ uint32_t smem_u32(const void* p) {
    uint32_t a;
    asm("{ .reg .u64 t; cvta.to.shared.u64 t, %1; cvt.u32.u64 %0, t; }" : "=r"(a) : "l"(p));
    return a;
}
__device__ __forceinline__ void sts64(uint32_t addr, uint32_t a, uint32_t b) {
    asm volatile("st.shared.v2.b32 [%0], {%1,%2};" :: "r"(addr), "r"(a), "r"(b));
}
#define LDSM4(r0,r1,r2,r3,addr) \
    asm volatile("ldmatrix.sync.aligned.m8n8.x4.shared.b16 {%0,%1,%2,%3}, [%4];" \
        : "=r"(r0),"=r"(r1),"=r"(r2),"=r"(r3) : "r"(addr))
#define LDSM4T(r0,r1,r2,r3,addr) \
    asm volatile("ldmatrix.sync.aligned.m8n8.x4.trans.shared.b16 {%0,%1,%2,%3}, [%4];" \
        : "=r"(r0),"=r"(r1),"=r"(r2),"=r"(r3) : "r"(addr))

__device__ __forceinline__ void mma16816(float& d0, float& d1, float& d2, float& d3,
                                         uint32_t a0, uint32_t a1, uint32_t a2, uint32_t a3,
                                         uint32_t b0, uint32_t b1) {
    asm volatile("mma.sync.aligned.m16n8k16.row.col.f32.bf16.bf16.f32 "
                 "{%0,%1,%2,%3}, {%4,%5,%6,%7}, {%8,%9}, {%0,%1,%2,%3};\n"
                 : "+f"(d0), "+f"(d1), "+f"(d2), "+f"(d3)
                 : "r"(a0), "r"(a1), "r"(a2), "r"(a3), "r"(b0), "r"(b1));
}

// split float4 into bf16 hi pair-packs + lo residual pair-packs (lo16 = first elem)
__device__ __forceinline__ void split4(float4 v, uint32_t& h0, uint32_t& h1,
                                       uint32_t& l0, uint32_t& l1) {
    asm("cvt.rn.bf16x2.f32 %0, %1, %2;" : "=r"(h0) : "f"(v.y), "f"(v.x));
    asm("cvt.rn.bf16x2.f32 %0, %1, %2;" : "=r"(h1) : "f"(v.w), "f"(v.z));
    float xh = __uint_as_float(h0 << 16), yh = __uint_as_float(h0 & 0xFFFF0000u);
    float zh = __uint_as_float(h1 << 16), wh = __uint_as_float(h1 & 0xFFFF0000u);
    float xl = v.x - xh, yl = v.y - yh, zl = v.z - zh, wl = v.w - wh;
    asm("cvt.rn.bf16x2.f32 %0, %1, %2;" : "=r"(l0) : "f"(yl), "f"(xl));
    asm("cvt.rn.bf16x2.f32 %0, %1, %2;" : "=r"(l1) : "f"(wl), "f"(zl));
}

__device__ __forceinline__ float silu_f(float z) { return z / (1.f + expf(-z)); }

// ---------------- small kernels ----------------
__global__ void zero_cnt_kernel() {
    if (threadIdx.x < E) g_cnt[threadIdx.x] = 0;
}

__global__ void router_kernel(const float* __restrict__ x,
                              const float* __restrict__ Wr,
                              const float* __restrict__ br, int N) {
    __shared__ float sWr[DM*E];
    for (int i = threadIdx.x; i < DM*E; i += blockDim.x) sWr[i] = Wr[i];
    __syncthreads();
    int warp = threadIdx.x >> 5, lane = threadIdx.x & 31;
    int tok = blockIdx.x * 8 + warp;
    if (tok >= N) return;
    const float* xr = x + (size_t)tok * DM;
    float acc[E];
#pragma unroll
    for (int e = 0; e < E; e++) acc[e] = 0.f;
    for (int d = lane; d < DM; d += 32) {
        float xv = xr[d];
#pragma unroll
        for (int e = 0; e < E; e++) acc[e] += xv * sWr[d*E + e];
    }
#pragma unroll
    for (int e = 0; e < E; e++) {
#pragma unroll
        for (int o = 16; o > 0; o >>= 1) acc[e] += __shfl_xor_sync(0xffffffffu, acc[e], o);
    }
    if (lane == 0) {
        float l[E]; float mx = -1e30f;
#pragma unroll
        for (int e = 0; e < E; e++) { l[e] = acc[e] + br[e]; mx = fmaxf(mx, l[e]); }
        float s = 0.f;
#pragma unroll
        for (int e = 0; e < E; e++) { l[e] = expf(l[e] - mx); s += l[e]; }
        int i1 = 0; float p1 = -1.f;
#pragma unroll
        for (int e = 0; e < E; e++) { if (l[e] > p1) { p1 = l[e]; i1 = e; } }
        int i2 = -1; float p2 = -1.f;
#pragma unroll
        for (int e = 0; e < E; e++) { if (e != i1 && l[e] > p2) { p2 = l[e]; i2 = e; } }
        float inv = 1.f / s;
        int m0 = tok * 2;
        int pos = atomicAdd(&g_cnt[i1], 1);
        g_bm[i1*MAXM + pos] = m0;     g_bg[i1*MAXM + pos] = p1 * inv;
        pos = atomicAdd(&g_cnt[i2], 1);
        g_bm[i2*MAXM + pos] = m0 + 1; g_bg[i2*MAXM + pos] = p2 * inv;
    }
}

#define RCH 1024
__global__ void rank_kernel(int cap) {
    __shared__ float sg[RCH];
    __shared__ int   sm[RCH];
    int e = blockIdx.y;
    int cnt = g_cnt[e];
    if (blockIdx.x == 0 && threadIdx.x == 0) g_kept[e] = min(cnt, cap);
    int i = blockIdx.x * blockDim.x + threadIdx.x;
    bool has = (i < cnt);
    float gi = has ? g_bg[e*MAXM + i] : 0.f;
    int   mi = has ? g_bm[e*MAXM + i] : 0;
    int rank = 0;
    for (int j0 = 0; j0 < cnt; j0 += RCH) {
        int nj = min(RCH, cnt - j0);
        __syncthreads();
        for (int j = threadIdx.x; j < nj; j += blockDim.x) {
            sg[j] = g_bg[e*MAXM + j0 + j];
            sm[j] = g_bm[e*MAXM + j0 + j];
        }
        __syncthreads();
        if (has) {
            for (int j = 0; j < nj; j++) {
                float gj = sg[j]; int mj = sm[j];
                rank += (gj > gi) || (gj == gi && mj < mi);
            }
        }
    }
    if (has && rank < cap) {
        g_disp_tok[e*CAPP + rank] = mi >> 1;
        g_disp_g[e*CAPP + rank]   = gi;
    }
}

// ---------------- GEMM (HMMA, ldmatrix, ping-pong smem) ----------------
// IS2==0: A = gathered x rows [BM,K=DM],  B = W1[e] [DM,HID], epi: silu(+b1)->g_h
// IS2==1: A = g_h rows [BM,K=HID],        B = W2[e] [HID,DM], epi: (+b2)*g -> atomicAdd Y
template <int KDIM, int NDIM, int IS2>
__global__ void __launch_bounds__(256, 1)
ffn_gemm_kernel(const float* __restrict__ X, const float* __restrict__ W,
                const float* __restrict__ Bias, float* __restrict__ Y) {
    extern __shared__ __align__(1024) char smem[];
    const uint32_t su = smem_u32(smem);
    const int tid = threadIdx.x, warp = tid >> 5, lane = tid & 31;
    const int e = blockIdx.z, m0 = blockIdx.y * BM, n0 = blockIdx.x * BN;
    const int kept = g_kept[e];

    int*   stok  = (int*)(smem + 2*STAGE);
    float* sgate = (float*)(smem + 2*STAGE + 512);
    if (tid < BM) {
        int r = m0 + tid; bool v = r < kept;
        stok[tid]  = v ? g_disp_tok[e*CAPP + r] : 0;
        sgate[tid] = v ? g_disp_g[e*CAPP + r]   : 0.f;
    }
    __syncthreads();

    // warp tiling: 2 warps along M (64 rows each), 4 along N (32 cols each)
    const int wm = (warp >> 2) * 64;
    const int wn = (warp & 3) * 32;
    const int q = lane >> 3, rr = lane & 7;
    const int gp = lane >> 2, tg = lane & 3;

    // ldmatrix lane base offsets
    const uint32_t a_base = (uint32_t)((wm + rr + (q & 1) * 8) * A_STRIDE + (q >> 1) * 16);
    const uint32_t b_base = (uint32_t)((rr + (q & 1) * 8) * B_STRIDE + (wn + (q >> 1) * 8) * 2);

    // producer mapping
    const int ar = tid >> 1, ak = (tid & 1) * 16;     // A: row, 16 k each
    const int kr = tid >> 3, nc = (tid & 7) * 4;      // B: k-row, n base
    bool a_valid;
    const float* ap0;
    if (IS2) { a_valid = true; ap0 = g_h + ((size_t)(e*CAPP + m0 + ar))*HID + ak; }
    else     { a_valid = (m0 + ar) < kept; ap0 = X + (size_t)stok[ar]*DM + ak; }
    const float* bp0 = W + (size_t)e*KDIM*NDIM + (size_t)kr*NDIM + n0 + nc;
    const uint32_t a_sts = (uint32_t)(ar * A_STRIDE + ak * 2);
    const uint32_t b_sts = (uint32_t)(kr * B_STRIDE + nc * 2);

    float D[4][4][4];
#pragma unroll
    for (int a = 0; a < 4; a++)
#pragma unroll
        for (int b = 0; b < 4; b++)
#pragma unroll
            for (int c = 0; c < 4; c++) D[a][b][c] = 0.f;

    float4 aS[4], bS[4];
    const int KCH = KDIM / BK;

#define LOADK(KT) do {                                                         \
    const float* _ap = ap0 + (KT)*BK;                                          \
    _Pragma("unroll")                                                          \
    for (int j = 0; j < 4; j++)                                                \
        aS[j] = a_valid ? __ldg((const float4*)(_ap + 4*j))                    \
                        : make_float4(0.f,0.f,0.f,0.f);                        \
    const float* _bp = bp0 + (size_t)(KT)*BK*NDIM;                             \
    _Pragma("unroll")                                                          \
    for (int j = 0; j < 4; j++)                                                \
        bS[j] = __ldg((const float4*)(_bp + 32*j));                            \
} while (0)

#define STSK(SB) do {                                                          \
    uint32_t _ah = (SB) + OFF_AHI + a_sts, _al = (SB) + OFF_ALO + a_sts;       \
    _Pragma("unroll")                                                          \
    for (int j = 0; j < 4; j++) {                                              \
        uint32_t h0,h1,l0,l1; split4(aS[j], h0,h1,l0,l1);                      \
        sts64(_ah + 8*j, h0, h1); sts64(_al + 8*j, l0, l1);                    \
    }                                                                          \
    uint32_t _bh = (SB) + OFF_BHI + b_sts, _bl = (SB) + OFF_BLO + b_sts;       \
    _Pragma("unroll")                                                          \
    for (int j = 0; j < 4; j++) {                                              \
        uint32_t h0,h1,l0,l1; split4(bS[j], h0,h1,l0,l1);                      \
        sts64(_bh + 64*j, h0, h1); sts64(_bl + 64*j, l0, l1);                  \
    }                                                                          \
} while (0)

    LOADK(0);
    STSK(su);
    __syncthreads();

#pragma unroll 1
    for (int kt = 0; kt < KCH; kt++) {
        if (kt + 1 < KCH) LOADK(kt + 1);
        const uint32_t sb = su + (uint32_t)(kt & 1) * STAGE;

#pragma unroll
        for (int kk = 0; kk < BK; kk += 16) {
            uint32_t Ah[4][4], Al[4][4], Bh[4][2], Bl[4][2];
            const uint32_t ah0 = sb + OFF_AHI + a_base + kk*2;
            const uint32_t al0 = sb + OFF_ALO + a_base + kk*2;
#pragma unroll
            for (int mt = 0; mt < 4; mt++) {
                LDSM4(Ah[mt][0],Ah[mt][1],Ah[mt][2],Ah[mt][3], ah0 + mt*16*A_STRIDE);
                LDSM4(Al[mt][0],Al[mt][1],Al[mt][2],Al[mt][3], al0 + mt*16*A_STRIDE);
            }
            const uint32_t bh0 = sb + OFF_BHI + b_base + kk*B_STRIDE;
            const uint32_t bl0 = sb + OFF_BLO + b_base + kk*B_STRIDE;
#pragma unroll
            for (int ntp = 0; ntp < 2; ntp++) {
                LDSM4T(Bh[ntp*2][0],Bh[ntp*2][1],Bh[ntp*2+1][0],Bh[ntp*2+1][1], bh0 + ntp*32);
                LDSM4T(Bl[ntp*2][0],Bl[ntp*2][1],Bl[ntp*2+1][0],Bl[ntp*2+1][1], bl0 + ntp*32);
            }
#pragma unroll
            for (int mt = 0; mt < 4; mt++)
#pragma unroll
                for (int nt = 0; nt < 4; nt++) {
                    mma16816(D[mt][nt][0], D[mt][nt][1], D[mt][nt][2], D[mt][nt][3],
                             Ah[mt][0], Ah[mt][1], Ah[mt][2], Ah[mt][3],
                             Bh[nt][0], Bh[nt][1]);
                    mma16816(D[mt][nt][0], D[mt][nt][1], D[mt][nt][2], D[mt][nt][3],
                             Ah[mt][0], Ah[mt][1], Ah[mt][2], Ah[mt][3],
                             Bl[nt][0], Bl[nt][1]);
                    mma16816(D[mt][nt][0], D[mt][nt][1], D[mt][nt][2], D[mt][nt][3],
                             Al[mt][0], Al[mt][1], Al[mt][2], Al[mt][3],
                             Bh[nt][0], Bh[nt][1]);
                }
        }
        if (kt + 1 < KCH) STSK(su + (uint32_t)((kt + 1) & 1) * STAGE);
        __syncthreads();
    }
#undef LOADK
#undef STSK

    // ---------------- epilogue ----------------
#pragma unroll
    for (int mt = 0; mt < 4; mt++) {
#pragma unroll
        for (int nt = 0; nt < 4; nt++) {
            int lr = wm + mt*16 + gp;
            int c  = wn + nt*8 + 2*tg;
            int gn = n0 + c;
            float2 bb = *(const float2*)&Bias[(size_t)e*NDIM + gn];
#pragma unroll
            for (int half = 0; half < 2; half++) {
                int lrow = lr + half*8;
                int r = m0 + lrow;
                float v0 = D[mt][nt][half*2 + 0];
                float v1 = D[mt][nt][half*2 + 1];
                if (!IS2) {
                    bool val = r < kept;
                    float o0 = val ? silu_f(v0 + bb.x) : 0.f;
                    float o1 = val ? silu_f(v1 + bb.y) : 0.f;
                    if (val) {
                        float2 o = make_float2(o0, o1);
                        *(float2*)&g_h[((size_t)(e*CAPP + r))*HID + gn] = o;
                    }
                } else {
                    if (r < kept) {
                        int tok = stok[lrow];
                        float g = sgate[lrow];
                        atomicAdd(&Y[(size_t)tok*DM + gn    ], (v0 + bb.x) * g);
                        atomicAdd(&Y[(size_t)tok*DM + gn + 1], (v1 + bb.y) * g);
                    }
                }
            }
        }
    }
}

// ---------------- launch ----------------
extern "C" void kernel_launch(void* const* d_in, const int* in_sizes, int n_in,
                              void* d_out, int out_size) {
    const float* x  = (const float*)d_in[0];
    const float* Wr = (const float*)d_in[1];
    const float* br = (const float*)d_in[2];
    const float* W1 = (const float*)d_in[3];
    const float* b1 = (const float*)d_in[4];
    const float* W2 = (const float*)d_in[5];
    const float* b2 = (const float*)d_in[6];
    float* y = (float*)d_out;

    int N = in_sizes[0] / DM;
    if (N > MAXN) N = MAXN;
    int cap = (int)ceil(1.2 * (double)N / (double)E);
    if (cap > CAPP) cap = CAPP;
    int mt = (cap + BM - 1) / BM;

    cudaFuncSetAttribute(ffn_gemm_kernel<DM, HID, 0>,
                         cudaFuncAttributeMaxDynamicSharedMemorySize, SMEM_TOTAL);
    cudaFuncSetAttribute(ffn_gemm_kernel<HID, DM, 1>,
                         cudaFuncAttributeMaxDynamicSharedMemorySize, SMEM_TOTAL);

    cudaMemsetAsync(y, 0, (size_t)out_size * sizeof(float));
    zero_cnt_kernel<<<1, 32>>>();
    router_kernel<<<(N + 7) / 8, 256>>>(x, Wr, br, N);

    dim3 rg((2 * N + 255) / 256, E);
    rank_kernel<<<rg, 256>>>(cap);

    dim3 g1(HID / BN, mt, E);
    ffn_gemm_kernel<DM, HID, 0><<<g1, 256, SMEM_TOTAL>>>(x, W1, b1, y);

    dim3 g2(DM / BN, mt, E);
    ffn_gemm_kernel<HID, DM, 1><<<g2, 256, SMEM_TOTAL>>>(x, W2, b2, y);
}

// round 4
// speedup vs baseline: 2.9683x; 1.1282x over previous
#include <cuda_runtime.h>
#include <math.h>
#include <stdint.h>

#define E 8
#define DM 1024
#define HID 4096
#define MAXN 16384
#define MAXM (MAXN*2)

#define BM 128
#define BN 256
#define BK 32
#define MTILES 20
#define CAPP (MTILES*BM)     // 2560 padded capacity rows per expert

// smem layout (bytes), per stage
#define A_STRIDE 80          // 40 fp16 per A row (128 rows)
#define B_STRIDE 528         // 264 fp16 per B k-row (32 rows)
#define OFF_AHI 0
#define OFF_ALO 10240
#define OFF_BHI 20480
#define STAGE   37376
#define SMEM_TOTAL (2*STAGE + 1024)

// ---------------- device scratch ----------------
__device__ int   g_cnt[E];
__device__ int   g_bm[E*MAXM];
__device__ float g_bg[E*MAXM];
__device__ int   g_disp_tok[E*CAPP];
__device__ float g_disp_g[E*CAPP];
__device__ int   g_kept[E];
__device__ float g_h[(size_t)E*CAPP*HID];

// ---------------- helpers ----------------
__device__ __forceinline__ uint32_t smem_u32(const void* p) {
    uint32_t a;
    asm("{ .reg .u64 t; cvta.to.shared.u64 t, %1; cvt.u32.u64 %0, t; }" : "=r"(a) : "l"(p));
    return a;
}
__device__ __forceinline__ void sts64(uint32_t addr, uint32_t a, uint32_t b) {
    asm volatile("st.shared.v2.b32 [%0], {%1,%2};" :: "r"(addr), "r"(a), "r"(b));
}
#define LDSM4(r0,r1,r2,r3,addr) \
    asm volatile("ldmatrix.sync.aligned.m8n8.x4.shared.b16 {%0,%1,%2,%3}, [%4];" \
        : "=r"(r0),"=r"(r1),"=r"(r2),"=r"(r3) : "r"(addr))
#define LDSM4T(r0,r1,r2,r3,addr) \
    asm volatile("ldmatrix.sync.aligned.m8n8.x4.trans.shared.b16 {%0,%1,%2,%3}, [%4];" \
        : "=r"(r0),"=r"(r1),"=r"(r2),"=r"(r3) : "r"(addr))

__device__ __forceinline__ void mma16816(float& d0, float& d1, float& d2, float& d3,
                                         uint32_t a0, uint32_t a1, uint32_t a2, uint32_t a3,
                                         uint32_t b0, uint32_t b1) {
    asm volatile("mma.sync.aligned.m16n8k16.row.col.f32.f16.f16.f32 "
                 "{%0,%1,%2,%3}, {%4,%5,%6,%7}, {%8,%9}, {%0,%1,%2,%3};\n"
                 : "+f"(d0), "+f"(d1), "+f"(d2), "+f"(d3)
                 : "r"(a0), "r"(a1), "r"(a2), "r"(a3), "r"(b0), "r"(b1));
}

// split float4 -> fp16 hi pair-packs + fp16 lo residual pair-packs
__device__ __forceinline__ void split4h(float4 v, uint32_t& h0, uint32_t& h1,
                                        uint32_t& l0, uint32_t& l1) {
    asm("cvt.rn.f16x2.f32 %0, %1, %2;" : "=r"(h0) : "f"(v.y), "f"(v.x));
    asm("cvt.rn.f16x2.f32 %0, %1, %2;" : "=r"(h1) : "f"(v.w), "f"(v.z));
    float xh, yh, zh, wh;
    asm("{ .reg .f16 a, b; mov.b32 {a, b}, %2; cvt.f32.f16 %0, a; cvt.f32.f16 %1, b; }"
        : "=f"(xh), "=f"(yh) : "r"(h0));
    asm("{ .reg .f16 a, b; mov.b32 {a, b}, %2; cvt.f32.f16 %0, a; cvt.f32.f16 %1, b; }"
        : "=f"(zh), "=f"(wh) : "r"(h1));
    float xl = v.x - xh, yl = v.y - yh, zl = v.z - zh, wl = v.w - wh;
    asm("cvt.rn.f16x2.f32 %0, %1, %2;" : "=r"(l0) : "f"(yl), "f"(xl));
    asm("cvt.rn.f16x2.f32 %0, %1, %2;" : "=r"(l1) : "f"(wl), "f"(zl));
}
__device__ __forceinline__ void cvt4h(float4 v, uint32_t& h0, uint32_t& h1) {
    asm("cvt.rn.f16x2.f32 %0, %1, %2;" : "=r"(h0) : "f"(v.y), "f"(v.x));
    asm("cvt.rn.f16x2.f32 %0, %1, %2;" : "=r"(h1) : "f"(v.w), "f"(v.z));
}

__device__ __forceinline__ float silu_f(float z) { return z / (1.f + expf(-z)); }

// ---------------- small kernels ----------------
__global__ void zero_cnt_kernel() {
    if (threadIdx.x < E) g_cnt[threadIdx.x] = 0;
}

__global__ void router_kernel(const float* __restrict__ x,
                              const float* __restrict__ Wr,
                              const float* __restrict__ br, int N) {
    __shared__ float sWr[DM*E];
    for (int i = threadIdx.x; i < DM*E; i += blockDim.x) sWr[i] = Wr[i];
    __syncthreads();
    int warp = threadIdx.x >> 5, lane = threadIdx.x & 31;
    int tok = blockIdx.x * 8 + warp;
    if (tok >= N) return;
    const float* xr = x + (size_t)tok * DM;
    float acc[E];
#pragma unroll
    for (int e = 0; e < E; e++) acc[e] = 0.f;
    for (int d = lane; d < DM; d += 32) {
        float xv = xr[d];
#pragma unroll
        for (int e = 0; e < E; e++) acc[e] += xv * sWr[d*E + e];
    }
#pragma unroll
    for (int e = 0; e < E; e++) {
#pragma unroll
        for (int o = 16; o > 0; o >>= 1) acc[e] += __shfl_xor_sync(0xffffffffu, acc[e], o);
    }
    if (lane == 0) {
        float l[E]; float mx = -1e30f;
#pragma unroll
        for (int e = 0; e < E; e++) { l[e] = acc[e] + br[e]; mx = fmaxf(mx, l[e]); }
        float s = 0.f;
#pragma unroll
        for (int e = 0; e < E; e++) { l[e] = expf(l[e] - mx); s += l[e]; }
        int i1 = 0; float p1 = -1.f;
#pragma unroll
        for (int e = 0; e < E; e++) { if (l[e] > p1) { p1 = l[e]; i1 = e; } }
        int i2 = -1; float p2 = -1.f;
#pragma unroll
        for (int e = 0; e < E; e++) { if (e != i1 && l[e] > p2) { p2 = l[e]; i2 = e; } }
        float inv = 1.f / s;
        int m0 = tok * 2;
        int pos = atomicAdd(&g_cnt[i1], 1);
        g_bm[i1*MAXM + pos] = m0;     g_bg[i1*MAXM + pos] = p1 * inv;
        pos = atomicAdd(&g_cnt[i2], 1);
        g_bm[i2*MAXM + pos] = m0 + 1; g_bg[i2*MAXM + pos] = p2 * inv;
    }
}

#define RCH 1024
__global__ void rank_kernel(int cap) {
    __shared__ float sg[RCH];
    __shared__ int   sm[RCH];
    int e = blockIdx.y;
    int cnt = g_cnt[e];
    if (blockIdx.x == 0 && threadIdx.x == 0) g_kept[e] = min(cnt, cap);
    int i = blockIdx.x * blockDim.x + threadIdx.x;
    bool has = (i < cnt);
    float gi = has ? g_bg[e*MAXM + i] : 0.f;
    int   mi = has ? g_bm[e*MAXM + i] : 0;
    int rank = 0;
    for (int j0 = 0; j0 < cnt; j0 += RCH) {
        int nj = min(RCH, cnt - j0);
        __syncthreads();
        for (int j = threadIdx.x; j < nj; j += blockDim.x) {
            sg[j] = g_bg[e*MAXM + j0 + j];
            sm[j] = g_bm[e*MAXM + j0 + j];
        }
        __syncthreads();
        if (has) {
            for (int j = 0; j < nj; j++) {
                float gj = sg[j]; int mj = sm[j];
                rank += (gj > gi) || (gj == gi && mj < mi);
            }
        }
    }
    if (has && rank < cap) {
        g_disp_tok[e*CAPP + rank] = mi >> 1;
        g_disp_g[e*CAPP + rank]   = gi;
    }
}

// ---------------- GEMM (fp16 HMMA x2, 64x64 warp tile) ----------------
// IS2==0: A = gathered x rows [BM,K=DM],  B = W1[e] [DM,HID], epi: silu(+b1)->g_h
// IS2==1: A = g_h rows [BM,K=HID],        B = W2[e] [HID,DM], epi: (+b2)*g -> atomicAdd Y
template <int KDIM, int NDIM, int IS2>
__global__ void __launch_bounds__(256, 1)
ffn_gemm_kernel(const float* __restrict__ X, const float* __restrict__ W,
                const float* __restrict__ Bias, float* __restrict__ Y) {
    extern __shared__ __align__(1024) char smem[];
    const uint32_t su = smem_u32(smem);
    const int tid = threadIdx.x, warp = tid >> 5, lane = tid & 31;
    const int e = blockIdx.z, m0 = blockIdx.y * BM, n0 = blockIdx.x * BN;
    const int kept = g_kept[e];

    int*   stok  = (int*)(smem + 2*STAGE);
    float* sgate = (float*)(smem + 2*STAGE + 512);
    if (tid < BM) {
        int r = m0 + tid; bool v = r < kept;
        stok[tid]  = v ? g_disp_tok[e*CAPP + r] : 0;
        sgate[tid] = v ? g_disp_g[e*CAPP + r]   : 0.f;
    }
    __syncthreads();

    // warp tiling: 2 warps along M (64 rows), 4 along N (64 cols) -> warp tile 64x64
    const int wm = (warp >> 2) * 64;
    const int wn = (warp & 3) * 64;
    const int q = lane >> 3, rr = lane & 7;
    const int gp = lane >> 2, tg = lane & 3;

    const uint32_t a_base = (uint32_t)((wm + rr + (q & 1) * 8) * A_STRIDE + (q >> 1) * 16);
    const uint32_t b_base = (uint32_t)((rr + (q & 1) * 8) * B_STRIDE + (wn + (q >> 1) * 8) * 2);

    // producer mapping
    const int ar = tid >> 1, ak = (tid & 1) * 16;     // A: 2 thr/row, 16 k each
    const int kr = tid >> 3, nc = (tid & 7) * 4;      // B: k-row, n base (8 thr cover 32 n)
    bool a_valid;
    const float* ap0;
    if (IS2) { a_valid = true; ap0 = g_h + ((size_t)(e*CAPP + m0 + ar))*HID + ak; }
    else     { a_valid = (m0 + ar) < kept; ap0 = X + (size_t)stok[ar]*DM + ak; }
    const float* bp0 = W + (size_t)e*KDIM*NDIM + (size_t)kr*NDIM + n0 + nc;
    const uint32_t a_sts = (uint32_t)(ar * A_STRIDE + ak * 2);
    const uint32_t b_sts = (uint32_t)(kr * B_STRIDE + nc * 2);

    float D[4][8][4];
#pragma unroll
    for (int a = 0; a < 4; a++)
#pragma unroll
        for (int b = 0; b < 8; b++)
#pragma unroll
            for (int c = 0; c < 4; c++) D[a][b][c] = 0.f;

    uint32_t Bh[8][2];
    float4 aS[4], bSa[4], bSb[4];
    const int KCH = KDIM / BK;

#define LOADA(KT) do {                                                         \
    const float* _p = ap0 + (KT)*BK;                                           \
    _Pragma("unroll")                                                          \
    for (int j = 0; j < 4; j++)                                                \
        aS[j] = a_valid ? __ldg((const float4*)(_p + 4*j))                     \
                        : make_float4(0.f,0.f,0.f,0.f);                        \
} while (0)
#define LOADB0(KT) do {                                                        \
    const float* _p = bp0 + (size_t)(KT)*BK*NDIM;                              \
    _Pragma("unroll")                                                          \
    for (int j = 0; j < 4; j++) bSa[j] = __ldg((const float4*)(_p + 32*j));    \
} while (0)
#define LOADB1(KT) do {                                                        \
    const float* _p = bp0 + (size_t)(KT)*BK*NDIM + 128;                        \
    _Pragma("unroll")                                                          \
    for (int j = 0; j < 4; j++) bSb[j] = __ldg((const float4*)(_p + 32*j));    \
} while (0)
#define STSA(SB) do {                                                          \
    uint32_t _h = (SB) + OFF_AHI + a_sts, _l = (SB) + OFF_ALO + a_sts;         \
    _Pragma("unroll")                                                          \
    for (int j = 0; j < 4; j++) {                                              \
        uint32_t h0,h1,l0,l1; split4h(aS[j], h0,h1,l0,l1);                     \
        sts64(_h + 8*j, h0, h1); sts64(_l + 8*j, l0, l1);                      \
    }                                                                          \
} while (0)
#define STSB0(SB) do {                                                         \
    uint32_t _b = (SB) + OFF_BHI + b_sts;                                      \
    _Pragma("unroll")                                                          \
    for (int j = 0; j < 4; j++) {                                              \
        uint32_t h0,h1; cvt4h(bSa[j], h0,h1); sts64(_b + 64*j, h0, h1);        \
    }                                                                          \
} while (0)
#define STSB1(SB) do {                                                         \
    uint32_t _b = (SB) + OFF_BHI + b_sts + 256;                                \
    _Pragma("unroll")                                                          \
    for (int j = 0; j < 4; j++) {                                              \
        uint32_t h0,h1; cvt4h(bSb[j], h0,h1); sts64(_b + 64*j, h0, h1);        \
    }                                                                          \
} while (0)
#define LDSMB(kk) do {                                                         \
    _Pragma("unroll")                                                          \
    for (int ntp = 0; ntp < 4; ntp++)                                          \
        LDSM4T(Bh[ntp*2][0],Bh[ntp*2][1],Bh[ntp*2+1][0],Bh[ntp*2+1][1],        \
               sb + OFF_BHI + b_base + (kk)*16*B_STRIDE + ntp*32);             \
} while (0)
#define MMA_MT(mt, kk) do {                                                    \
    uint32_t Ah0,Ah1,Ah2,Ah3, Al0,Al1,Al2,Al3;                                 \
    uint32_t _aa = sb + OFF_AHI + a_base + (mt)*16*A_STRIDE + (kk)*32;         \
    uint32_t _la = sb + OFF_ALO + a_base + (mt)*16*A_STRIDE + (kk)*32;         \
    LDSM4(Ah0,Ah1,Ah2,Ah3, _aa);                                               \
    LDSM4(Al0,Al1,Al2,Al3, _la);                                               \
    _Pragma("unroll")                                                          \
    for (int nt = 0; nt < 8; nt++)                                             \
        mma16816(D[mt][nt][0],D[mt][nt][1],D[mt][nt][2],D[mt][nt][3],          \
                 Ah0,Ah1,Ah2,Ah3, Bh[nt][0],Bh[nt][1]);                        \
    _Pragma("unroll")                                                          \
    for (int nt = 0; nt < 8; nt++)                                             \
        mma16816(D[mt][nt][0],D[mt][nt][1],D[mt][nt][2],D[mt][nt][3],          \
                 Al0,Al1,Al2,Al3, Bh[nt][0],Bh[nt][1]);                        \
} while (0)

    LOADA(0); LOADB0(0); LOADB1(0);
    STSA(su); STSB0(su); STSB1(su);
    __syncthreads();

#pragma unroll 1
    for (int kt = 0; kt < KCH; kt++) {
        const uint32_t sb = su + (uint32_t)(kt & 1) * STAGE;
        const uint32_t nx = su + (uint32_t)((kt + 1) & 1) * STAGE;
        const bool more = (kt + 1 < KCH);
        LDSMB(0);
        if (more) LOADB0(kt + 1);
        MMA_MT(0,0); MMA_MT(1,0);
        if (more) { STSB0(nx); LOADB1(kt + 1); }
        MMA_MT(2,0); MMA_MT(3,0);
        if (more) { STSB1(nx); LOADA(kt + 1); }
        LDSMB(1);
        MMA_MT(0,1); MMA_MT(1,1);
        if (more) STSA(nx);
        MMA_MT(2,1); MMA_MT(3,1);
        __syncthreads();
    }
#undef LOADA
#undef LOADB0
#undef LOADB1
#undef STSA
#undef STSB0
#undef STSB1
#undef LDSMB
#undef MMA_MT

    // ---------------- epilogue ----------------
#pragma unroll
    for (int mt = 0; mt < 4; mt++) {
#pragma unroll
        for (int nt = 0; nt < 8; nt++) {
            int lr = wm + mt*16 + gp;
            int c  = wn + nt*8 + 2*tg;
            int gn = n0 + c;
            float2 bb = *(const float2*)&Bias[(size_t)e*NDIM + gn];
#pragma unroll
            for (int half = 0; half < 2; half++) {
                int lrow = lr + half*8;
                int r = m0 + lrow;
                float v0 = D[mt][nt][half*2 + 0];
                float v1 = D[mt][nt][half*2 + 1];
                if (!IS2) {
                    if (r < kept) {
                        float2 o = make_float2(silu_f(v0 + bb.x), silu_f(v1 + bb.y));
                        *(float2*)&g_h[((size_t)(e*CAPP + r))*HID + gn] = o;
                    }
                } else {
                    if (r < kept) {
                        int tok = stok[lrow];
                        float g = sgate[lrow];
                        atomicAdd(&Y[(size_t)tok*DM + gn    ], (v0 + bb.x) * g);
                        atomicAdd(&Y[(size_t)tok*DM + gn + 1], (v1 + bb.y) * g);
                    }
                }
            }
        }
    }
}

// ---------------- launch ----------------
extern "C" void kernel_launch(void* const* d_in, const int* in_sizes, int n_in,
                              void* d_out, int out_size) {
    const float* x  = (const float*)d_in[0];
    const float* Wr = (const float*)d_in[1];
    const float* br = (const float*)d_in[2];
    const float* W1 = (const float*)d_in[3];
    const float* b1 = (const float*)d_in[4];
    const float* W2 = (const float*)d_in[5];
    const float* b2 = (const float*)d_in[6];
    float* y = (float*)d_out;

    int N = in_sizes[0] / DM;
    if (N > MAXN) N = MAXN;
    int cap = (int)ceil(1.2 * (double)N / (double)E);
    if (cap > CAPP) cap = CAPP;
    int mt = (cap + BM - 1) / BM;

    cudaFuncSetAttribute(ffn_gemm_kernel<DM, HID, 0>,
                         cudaFuncAttributeMaxDynamicSharedMemorySize, SMEM_TOTAL);
    cudaFuncSetAttribute(ffn_gemm_kernel<HID, DM, 1>,
                         cudaFuncAttributeMaxDynamicSharedMemorySize, SMEM_TOTAL);

    cudaMemsetAsync(y, 0, (size_t)out_size * sizeof(float));
    zero_cnt_kernel<<<1, 32>>>();
    router_kernel<<<(N + 7) / 8, 256>>>(x, Wr, br, N);

    dim3 rg((2 * N + 255) / 256, E);
    rank_kernel<<<rg, 256>>>(cap);

    dim3 g1(HID / BN, mt, E);
    ffn_gemm_kernel<DM, HID, 0><<<g1, 256, SMEM_TOTAL>>>(x, W1, b1, y);

    dim3 g2(DM / BN, mt, E);
    ffn_gemm_kernel<HID, DM, 1><<<g2, 256, SMEM_TOTAL>>>(x, W2, b2, y);
}

// round 5
// speedup vs baseline: 3.6316x; 1.2235x over previous
#include <cuda_runtime.h>
#include <cuda_fp16.h>
#include <math.h>
#include <stdint.h>

#define E 8
#define DM 1024
#define HID 4096
#define MAXN 16384
#define MAXM (MAXN*2)

#define BM 128
#define BN 256
#define BK 32
#define MTILES 20
#define CAPP (MTILES*BM)     // 2560 padded capacity rows per expert

// smem layout (bytes), per stage
#define A_STRIDE 80          // 40 fp16 per A row (32 data + pad), 128 rows
#define B_STRIDE 528         // 264 fp16 per B k-row (256 data + pad), 32 rows
#define OFF_AHI 0
#define OFF_ALO 10240
#define OFF_BHI 20480
#define STAGE   37376
#define NSTAGE  4
#define SMEM_TOTAL (NSTAGE*STAGE + 1024)

// ---------------- device scratch ----------------
__device__ int    g_cnt[E];
__device__ int    g_bm[E*MAXM];
__device__ float  g_bg[E*MAXM];
__device__ int    g_disp_tok[E*CAPP];
__device__ float  g_disp_g[E*CAPP];
__device__ int    g_kept[E];
__device__ __half g_w1h[(size_t)E*DM*HID];
__device__ __half g_w2h[(size_t)E*HID*DM];
__device__ __half g_xg_hi[(size_t)E*CAPP*DM];
__device__ __half g_xg_lo[(size_t)E*CAPP*DM];
__device__ __half g_h_hi[(size_t)E*CAPP*HID];
__device__ __half g_h_lo[(size_t)E*CAPP*HID];

// ---------------- helpers ----------------
__device__ __forceinline__ uint32_t smem_u32(const void* p) {
    uint32_t a;
    asm("{ .reg .u64 t; cvta.to.shared.u64 t, %1; cvt.u32.u64 %0, t; }" : "=r"(a) : "l"(p));
    return a;
}
#define CPA(s, g) \
    asm volatile("cp.async.cg.shared.global [%0], [%1], 16;" :: "r"(s), "l"(g))
#define CPA_COMMIT() asm volatile("cp.async.commit_group;" ::: "memory")
#define CPA_WAIT2()  asm volatile("cp.async.wait_group 2;" ::: "memory")

#define LDSM4(r0,r1,r2,r3,addr) \
    asm volatile("ldmatrix.sync.aligned.m8n8.x4.shared.b16 {%0,%1,%2,%3}, [%4];" \
        : "=r"(r0),"=r"(r1),"=r"(r2),"=r"(r3) : "r"(addr))
#define LDSM4T(r0,r1,r2,r3,addr) \
    asm volatile("ldmatrix.sync.aligned.m8n8.x4.trans.shared.b16 {%0,%1,%2,%3}, [%4];" \
        : "=r"(r0),"=r"(r1),"=r"(r2),"=r"(r3) : "r"(addr))

__device__ __forceinline__ void mma16816(float& d0, float& d1, float& d2, float& d3,
                                         uint32_t a0, uint32_t a1, uint32_t a2, uint32_t a3,
                                         uint32_t b0, uint32_t b1) {
    asm volatile("mma.sync.aligned.m16n8k16.row.col.f32.f16.f16.f32 "
                 "{%0,%1,%2,%3}, {%4,%5,%6,%7}, {%8,%9}, {%0,%1,%2,%3};\n"
                 : "+f"(d0), "+f"(d1), "+f"(d2), "+f"(d3)
                 : "r"(a0), "r"(a1), "r"(a2), "r"(a3), "r"(b0), "r"(b1));
}

__device__ __forceinline__ float silu_f(float z) { return z / (1.f + expf(-z)); }

// ---------------- small kernels ----------------
__global__ void zero_cnt_kernel() {
    if (threadIdx.x < E) g_cnt[threadIdx.x] = 0;
}

__global__ void router_kernel(const float* __restrict__ x,
                              const float* __restrict__ Wr,
                              const float* __restrict__ br, int N) {
    __shared__ float sWr[DM*E];
    for (int i = threadIdx.x; i < DM*E; i += blockDim.x) sWr[i] = Wr[i];
    __syncthreads();
    int warp = threadIdx.x >> 5, lane = threadIdx.x & 31;
    int tok = blockIdx.x * 8 + warp;
    if (tok >= N) return;
    const float* xr = x + (size_t)tok * DM;
    float acc[E];
#pragma unroll
    for (int e = 0; e < E; e++) acc[e] = 0.f;
    for (int d = lane; d < DM; d += 32) {
        float xv = xr[d];
#pragma unroll
        for (int e = 0; e < E; e++) acc[e] += xv * sWr[d*E + e];
    }
#pragma unroll
    for (int e = 0; e < E; e++) {
#pragma unroll
        for (int o = 16; o > 0; o >>= 1) acc[e] += __shfl_xor_sync(0xffffffffu, acc[e], o);
    }
    if (lane == 0) {
        float l[E]; float mx = -1e30f;
#pragma unroll
        for (int e = 0; e < E; e++) { l[e] = acc[e] + br[e]; mx = fmaxf(mx, l[e]); }
        float s = 0.f;
#pragma unroll
        for (int e = 0; e < E; e++) { l[e] = expf(l[e] - mx); s += l[e]; }
        int i1 = 0; float p1 = -1.f;
#pragma unroll
        for (int e = 0; e < E; e++) { if (l[e] > p1) { p1 = l[e]; i1 = e; } }
        int i2 = -1; float p2 = -1.f;
#pragma unroll
        for (int e = 0; e < E; e++) { if (e != i1 && l[e] > p2) { p2 = l[e]; i2 = e; } }
        float inv = 1.f / s;
        int m0 = tok * 2;
        int pos = atomicAdd(&g_cnt[i1], 1);
        g_bm[i1*MAXM + pos] = m0;     g_bg[i1*MAXM + pos] = p1 * inv;
        pos = atomicAdd(&g_cnt[i2], 1);
        g_bm[i2*MAXM + pos] = m0 + 1; g_bg[i2*MAXM + pos] = p2 * inv;
    }
}

#define RCH 1024
__global__ void rank_kernel(int cap) {
    __shared__ float sg[RCH];
    __shared__ int   sm[RCH];
    int e = blockIdx.y;
    int cnt = g_cnt[e];
    if (blockIdx.x == 0 && threadIdx.x == 0) g_kept[e] = min(cnt, cap);
    int i = blockIdx.x * blockDim.x + threadIdx.x;
    bool has = (i < cnt);
    float gi = has ? g_bg[e*MAXM + i] : 0.f;
    int   mi = has ? g_bm[e*MAXM + i] : 0;
    int rank = 0;
    for (int j0 = 0; j0 < cnt; j0 += RCH) {
        int nj = min(RCH, cnt - j0);
        __syncthreads();
        for (int j = threadIdx.x; j < nj; j += blockDim.x) {
            sg[j] = g_bg[e*MAXM + j0 + j];
            sm[j] = g_bm[e*MAXM + j0 + j];
        }
        __syncthreads();
        if (has) {
            for (int j = 0; j < nj; j++) {
                float gj = sg[j]; int mj = sm[j];
                rank += (gj > gi) || (gj == gi && mj < mi);
            }
        }
    }
    if (has && rank < cap) {
        g_disp_tok[e*CAPP + rank] = mi >> 1;
        g_disp_g[e*CAPP + rank]   = gi;
    }
}

// weights fp32 -> fp16 (grid-stride over float4)
__global__ void wconv_kernel(const float* __restrict__ W, __half* __restrict__ out, int n4) {
    int i = blockIdx.x * blockDim.x + threadIdx.x;
    int stride = gridDim.x * blockDim.x;
    for (; i < n4; i += stride) {
        float4 v = __ldg(&((const float4*)W)[i]);
        uint32_t h0, h1;
        asm("cvt.rn.f16x2.f32 %0, %1, %2;" : "=r"(h0) : "f"(v.y), "f"(v.x));
        asm("cvt.rn.f16x2.f32 %0, %1, %2;" : "=r"(h1) : "f"(v.w), "f"(v.z));
        uint2 o; o.x = h0; o.y = h1;
        ((uint2*)out)[i] = o;
    }
}

// gather dispatched rows of x -> fp16 hi/lo planes (zero-filled beyond kept)
__global__ void gather_kernel(const float* __restrict__ x) {
    int e = blockIdx.y;
    int warp = threadIdx.x >> 5, lane = threadIdx.x & 31;
    int r = blockIdx.x * 8 + warp;
    int kept = g_kept[e];
    bool v = r < kept;
    int tok = v ? g_disp_tok[e*CAPP + r] : 0;
    const float* src = x + (size_t)tok * DM;
    size_t dst = (size_t)(e*CAPP + r) * DM;
    for (int d = lane * 4; d < DM; d += 128) {
        float4 val = v ? __ldg((const float4*)(src + d)) : make_float4(0.f,0.f,0.f,0.f);
        uint32_t h0, h1;
        asm("cvt.rn.f16x2.f32 %0, %1, %2;" : "=r"(h0) : "f"(val.y), "f"(val.x));
        asm("cvt.rn.f16x2.f32 %0, %1, %2;" : "=r"(h1) : "f"(val.w), "f"(val.z));
        float xh, yh, zh, wh;
        asm("{ .reg .f16 a, b; mov.b32 {a, b}, %2; cvt.f32.f16 %0, a; cvt.f32.f16 %1, b; }"
            : "=f"(xh), "=f"(yh) : "r"(h0));
        asm("{ .reg .f16 a, b; mov.b32 {a, b}, %2; cvt.f32.f16 %0, a; cvt.f32.f16 %1, b; }"
            : "=f"(zh), "=f"(wh) : "r"(h1));
        float xl = val.x - xh, yl = val.y - yh, zl = val.z - zh, wl = val.w - wh;
        uint32_t l0, l1;
        asm("cvt.rn.f16x2.f32 %0, %1, %2;" : "=r"(l0) : "f"(yl), "f"(xl));
        asm("cvt.rn.f16x2.f32 %0, %1, %2;" : "=r"(l1) : "f"(wl), "f"(zl));
        uint2 oh; oh.x = h0; oh.y = h1;
        uint2 ol; ol.x = l0; ol.y = l1;
        *(uint2*)&g_xg_hi[dst + d] = oh;
        *(uint2*)&g_xg_lo[dst + d] = ol;
    }
}

// ---------------- GEMM (fp16 HMMA, cp.async 4-stage pipeline) ----------------
// IS2==0: A = g_xg (hi/lo) [*,DM],  B = g_w1h [DM,HID], epi: silu(+b1) -> g_h_hi/lo
// IS2==1: A = g_h (hi/lo) [*,HID],  B = g_w2h [HID,DM], epi: (+b2)*g -> atomicAdd Y
template <int KDIM, int NDIM, int IS2>
__global__ void __launch_bounds__(256, 1)
ffn_gemm_kernel(const __half* __restrict__ Ahi, const __half* __restrict__ Alo,
                const __half* __restrict__ W, const float* __restrict__ Bias,
                float* __restrict__ Y) {
    extern __shared__ __align__(1024) char smem[];
    const uint32_t su = smem_u32(smem);
    const int tid = threadIdx.x, warp = tid >> 5, lane = tid & 31;
    const int e = blockIdx.z, m0 = blockIdx.y * BM, n0 = blockIdx.x * BN;
    const int kept = g_kept[e];

    int*   stok  = (int*)(smem + NSTAGE*STAGE);
    float* sgate = (float*)(smem + NSTAGE*STAGE + 512);
    if (tid < BM) {
        int r = m0 + tid; bool v = r < kept;
        stok[tid]  = v ? g_disp_tok[e*CAPP + r] : 0;
        sgate[tid] = v ? g_disp_g[e*CAPP + r]   : 0.f;
    }

    // warp tiling: 2 warps along M (64 rows), 4 along N (64 cols)
    const int wm = (warp >> 2) * 64;
    const int wn = (warp & 3) * 64;
    const int q = lane >> 3, rr = lane & 7;
    const int gp = lane >> 2, tg = lane & 3;

    const uint32_t a_base = (uint32_t)((wm + rr + (q & 1) * 8) * A_STRIDE + (q >> 1) * 16);
    const uint32_t b_base = (uint32_t)((rr + (q & 1) * 8) * B_STRIDE + (wn + (q >> 1) * 8) * 2);

    // producer (cp.async) mapping
    const int a_row = tid >> 2, a_kc = tid & 3;       // rows a_row, a_row+64; 16B chunk a_kc
    const int b_row = tid >> 5, b_nc = tid & 31;      // rows b_row + {0,8,16,24}
    const uint32_t a_cs = (uint32_t)(a_row * A_STRIDE + a_kc * 16);
    const uint32_t b_cs = (uint32_t)(b_row * B_STRIDE + b_nc * 16);
    const __half* Ahi_t = Ahi + (size_t)(e*CAPP + m0 + a_row)*KDIM + a_kc*8;
    const __half* Alo_t = Alo + (size_t)(e*CAPP + m0 + a_row)*KDIM + a_kc*8;
    const __half* Bt    = W + (size_t)e*KDIM*NDIM + (size_t)b_row*NDIM + n0 + b_nc*8;

    float D[4][8][4];
#pragma unroll
    for (int a = 0; a < 4; a++)
#pragma unroll
        for (int b = 0; b < 8; b++)
#pragma unroll
            for (int c = 0; c < 4; c++) D[a][b][c] = 0.f;

    uint32_t Bh[8][2];
    const int KCH = KDIM / BK;

#define ISSUE(KT, SB) do {                                                     \
    const __half* _ah = Ahi_t + (size_t)(KT)*BK;                               \
    const __half* _al = Alo_t + (size_t)(KT)*BK;                               \
    CPA((SB) + OFF_AHI + a_cs, _ah);                                           \
    CPA((SB) + OFF_AHI + a_cs + 64*A_STRIDE, _ah + (size_t)64*KDIM);           \
    CPA((SB) + OFF_ALO + a_cs, _al);                                           \
    CPA((SB) + OFF_ALO + a_cs + 64*A_STRIDE, _al + (size_t)64*KDIM);           \
    const __half* _b = Bt + (size_t)(KT)*BK*NDIM;                              \
    _Pragma("unroll")                                                          \
    for (int j = 0; j < 4; j++)                                                \
        CPA((SB) + OFF_BHI + b_cs + j*8*B_STRIDE, _b + (size_t)j*8*NDIM);      \
} while (0)

#define LDSMB(kk) do {                                                         \
    _Pragma("unroll")                                                          \
    for (int ntp = 0; ntp < 4; ntp++)                                          \
        LDSM4T(Bh[ntp*2][0],Bh[ntp*2][1],Bh[ntp*2+1][0],Bh[ntp*2+1][1],        \
               sb + OFF_BHI + b_base + (kk)*16*B_STRIDE + ntp*32);             \
} while (0)
#define MMA_MT(mt, kk) do {                                                    \
    uint32_t Ah0,Ah1,Ah2,Ah3, Al0,Al1,Al2,Al3;                                 \
    uint32_t _aa = sb + OFF_AHI + a_base + (mt)*16*A_STRIDE + (kk)*32;         \
    uint32_t _la = sb + OFF_ALO + a_base + (mt)*16*A_STRIDE + (kk)*32;         \
    LDSM4(Ah0,Ah1,Ah2,Ah3, _aa);                                               \
    LDSM4(Al0,Al1,Al2,Al3, _la);                                               \
    _Pragma("unroll")                                                          \
    for (int nt = 0; nt < 8; nt++)                                             \
        mma16816(D[mt][nt][0],D[mt][nt][1],D[mt][nt][2],D[mt][nt][3],          \
                 Ah0,Ah1,Ah2,Ah3, Bh[nt][0],Bh[nt][1]);                        \
    _Pragma("unroll")                                                          \
    for (int nt = 0; nt < 8; nt++)                                             \
        mma16816(D[mt][nt][0],D[mt][nt][1],D[mt][nt][2],D[mt][nt][3],          \
                 Al0,Al1,Al2,Al3, Bh[nt][0],Bh[nt][1]);                        \
} while (0)

    // prologue: 3 stages in flight
    ISSUE(0, su + 0*STAGE); CPA_COMMIT();
    ISSUE(1, su + 1*STAGE); CPA_COMMIT();
    ISSUE(2, su + 2*STAGE); CPA_COMMIT();

#pragma unroll 1
    for (int kt = 0; kt < KCH; kt++) {
        CPA_WAIT2();
        __syncthreads();
        const uint32_t sb = su + (uint32_t)(kt & (NSTAGE-1)) * STAGE;
        if (kt + 3 < KCH) ISSUE(kt + 3, su + (uint32_t)((kt + 3) & (NSTAGE-1)) * STAGE);
        CPA_COMMIT();
        LDSMB(0);
        MMA_MT(0,0); MMA_MT(1,0); MMA_MT(2,0); MMA_MT(3,0);
        LDSMB(1);
        MMA_MT(0,1); MMA_MT(1,1); MMA_MT(2,1); MMA_MT(3,1);
    }
#undef ISSUE
#undef LDSMB
#undef MMA_MT

    // ---------------- epilogue ----------------
#pragma unroll
    for (int mt = 0; mt < 4; mt++) {
#pragma unroll
        for (int nt = 0; nt < 8; nt++) {
            int lr = wm + mt*16 + gp;
            int c  = wn + nt*8 + 2*tg;
            int gn = n0 + c;
            float2 bb = *(const float2*)&Bias[(size_t)e*NDIM + gn];
#pragma unroll
            for (int half = 0; half < 2; half++) {
                int lrow = lr + half*8;
                int r = m0 + lrow;
                float v0 = D[mt][nt][half*2 + 0];
                float v1 = D[mt][nt][half*2 + 1];
                if (!IS2) {
                    if (r < kept) {
                        float o0 = silu_f(v0 + bb.x), o1 = silu_f(v1 + bb.y);
                        __half h0 = __float2half_rn(o0), h1 = __float2half_rn(o1);
                        __half l0 = __float2half_rn(o0 - __half2float(h0));
                        __half l1 = __float2half_rn(o1 - __half2float(h1));
                        size_t idx = (size_t)(e*CAPP + r)*HID + gn;
                        *(__half2*)&g_h_hi[idx] = __halves2half2(h0, h1);
                        *(__half2*)&g_h_lo[idx] = __halves2half2(l0, l1);
                    }
                } else {
                    if (r < kept) {
                        int tok = stok[lrow];
                        float g = sgate[lrow];
                        atomicAdd(&Y[(size_t)tok*DM + gn    ], (v0 + bb.x) * g);
                        atomicAdd(&Y[(size_t)tok*DM + gn + 1], (v1 + bb.y) * g);
                    }
                }
            }
        }
    }
}

// ---------------- launch ----------------
extern "C" void kernel_launch(void* const* d_in, const int* in_sizes, int n_in,
                              void* d_out, int out_size) {
    const float* x  = (const float*)d_in[0];
    const float* Wr = (const float*)d_in[1];
    const float* br = (const float*)d_in[2];
    const float* W1 = (const float*)d_in[3];
    const float* b1 = (const float*)d_in[4];
    const float* W2 = (const float*)d_in[5];
    const float* b2 = (const float*)d_in[6];
    float* y = (float*)d_out;

    int N = in_sizes[0] / DM;
    if (N > MAXN) N = MAXN;
    int cap = (int)ceil(1.2 * (double)N / (double)E);
    if (cap > CAPP) cap = CAPP;
    int mt = (cap + BM - 1) / BM;

    cudaFuncSetAttribute(ffn_gemm_kernel<DM, HID, 0>,
                         cudaFuncAttributeMaxDynamicSharedMemorySize, SMEM_TOTAL);
    cudaFuncSetAttribute(ffn_gemm_kernel<HID, DM, 1>,
                         cudaFuncAttributeMaxDynamicSharedMemorySize, SMEM_TOTAL);

    cudaMemsetAsync(y, 0, (size_t)out_size * sizeof(float));
    zero_cnt_kernel<<<1, 32>>>();

    // weight conversion (independent of routing)
    __half* w1h; cudaGetSymbolAddress((void**)&w1h, g_w1h);
    __half* w2h; cudaGetSymbolAddress((void**)&w2h, g_w2h);
    const int n4 = (E*DM*HID) / 4;
    wconv_kernel<<<4096, 256>>>(W1, w1h, n4);
    wconv_kernel<<<4096, 256>>>(W2, w2h, n4);

    router_kernel<<<(N + 7) / 8, 256>>>(x, Wr, br, N);
    dim3 rg((2 * N + 255) / 256, E);
    rank_kernel<<<rg, 256>>>(cap);

    dim3 gg(CAPP / 8, E);
    gather_kernel<<<gg, 256>>>(x);

    __half* xgh; cudaGetSymbolAddress((void**)&xgh, g_xg_hi);
    __half* xgl; cudaGetSymbolAddress((void**)&xgl, g_xg_lo);
    __half* hh;  cudaGetSymbolAddress((void**)&hh,  g_h_hi);
    __half* hl;  cudaGetSymbolAddress((void**)&hl,  g_h_lo);

    dim3 g1(HID / BN, mt, E);
    ffn_gemm_kernel<DM, HID, 0><<<g1, 256, SMEM_TOTAL>>>(xgh, xgl, w1h, b1, y);

    dim3 g2(DM / BN, mt, E);
    ffn_gemm_kernel<HID, DM, 1><<<g2, 256, SMEM_TOTAL>>>(hh, hl, w2h, b2, y);
}

// round 6
// speedup vs baseline: 5.4469x; 1.4999x over previous
#include <cuda_runtime.h>
#include <cuda_fp16.h>
#include <math.h>
#include <stdint.h>

#define E 8
#define DM 1024
#define HID 4096
#define MAXN 16384
#define MAXM (MAXN*2)

#define BM 128
#define BN 256
#define BK 32
#define MTILES 20
#define CAPP (MTILES*BM)     // 2560 padded capacity rows per expert

// smem layout (bytes), per stage
#define A_STRIDE 80          // 40 fp16 per A row (32 data + pad), 128 rows
#define B_STRIDE 528         // 264 fp16 per B k-row (256 data + pad), 32 rows
#define OFF_A 0
#define OFF_B 10240
#define STAGE   27136
#define NSTAGE  4
#define SMEM_TOTAL (NSTAGE*STAGE + 1024)

// ---------------- device scratch ----------------
__device__ int    g_cnt[E];
__device__ int    g_bm[E*MAXM];
__device__ float  g_bg[E*MAXM];
__device__ int    g_disp_tok[E*CAPP];
__device__ float  g_disp_g[E*CAPP];
__device__ int    g_kept[E];
__device__ __half g_w1h[(size_t)E*DM*HID];
__device__ __half g_w2h[(size_t)E*HID*DM];
__device__ __half g_xg[(size_t)E*CAPP*DM];
__device__ __half g_h[(size_t)E*CAPP*HID];

// ---------------- helpers ----------------
__device__ __forceinline__ uint32_t smem_u32(const void* p) {
    uint32_t a;
    asm("{ .reg .u64 t; cvta.to.shared.u64 t, %1; cvt.u32.u64 %0, t; }" : "=r"(a) : "l"(p));
    return a;
}
#define CPA(s, g) \
    asm volatile("cp.async.cg.shared.global [%0], [%1], 16;" :: "r"(s), "l"(g))
#define CPA_COMMIT() asm volatile("cp.async.commit_group;" ::: "memory")
#define CPA_WAIT2()  asm volatile("cp.async.wait_group 2;" ::: "memory")

#define LDSM4(r0,r1,r2,r3,addr) \
    asm volatile("ldmatrix.sync.aligned.m8n8.x4.shared.b16 {%0,%1,%2,%3}, [%4];" \
        : "=r"(r0),"=r"(r1),"=r"(r2),"=r"(r3) : "r"(addr))
#define LDSM4T(r0,r1,r2,r3,addr) \
    asm volatile("ldmatrix.sync.aligned.m8n8.x4.trans.shared.b16 {%0,%1,%2,%3}, [%4];" \
        : "=r"(r0),"=r"(r1),"=r"(r2),"=r"(r3) : "r"(addr))

__device__ __forceinline__ void mma16816(float& d0, float& d1, float& d2, float& d3,
                                         uint32_t a0, uint32_t a1, uint32_t a2, uint32_t a3,
                                         uint32_t b0, uint32_t b1) {
    asm volatile("mma.sync.aligned.m16n8k16.row.col.f32.f16.f16.f32 "
                 "{%0,%1,%2,%3}, {%4,%5,%6,%7}, {%8,%9}, {%0,%1,%2,%3};\n"
                 : "+f"(d0), "+f"(d1), "+f"(d2), "+f"(d3)
                 : "r"(a0), "r"(a1), "r"(a2), "r"(a3), "r"(b0), "r"(b1));
}

__device__ __forceinline__ float silu_f(float z) { return z / (1.f + expf(-z)); }

// ---------------- small kernels ----------------
__global__ void zero_cnt_kernel() {
    if (threadIdx.x < E) g_cnt[threadIdx.x] = 0;
}

#define WRS 9   // padded stride (coprime with 32 -> conflict-free LDS)
__global__ void router_kernel(const float* __restrict__ x,
                              const float* __restrict__ Wr,
                              const float* __restrict__ br, int N) {
    __shared__ float sWr[DM*WRS];
    for (int i = threadIdx.x; i < DM*E; i += blockDim.x) {
        int d = i >> 3, e = i & 7;
        sWr[d*WRS + e] = Wr[i];
    }
    __syncthreads();
    int warp = threadIdx.x >> 5, lane = threadIdx.x & 31;
    int tok = blockIdx.x * 8 + warp;
    if (tok >= N) return;
    const float* xr = x + (size_t)tok * DM;
    float acc[E];
#pragma unroll
    for (int e = 0; e < E; e++) acc[e] = 0.f;
    for (int d = lane; d < DM; d += 32) {
        float xv = __ldg(xr + d);
        const float* w = sWr + d*WRS;
#pragma unroll
        for (int e = 0; e < E; e++) acc[e] += xv * w[e];
    }
#pragma unroll
    for (int e = 0; e < E; e++) {
#pragma unroll
        for (int o = 16; o > 0; o >>= 1) acc[e] += __shfl_xor_sync(0xffffffffu, acc[e], o);
    }
    if (lane == 0) {
        float l[E]; float mx = -1e30f;
#pragma unroll
        for (int e = 0; e < E; e++) { l[e] = acc[e] + br[e]; mx = fmaxf(mx, l[e]); }
        float s = 0.f;
#pragma unroll
        for (int e = 0; e < E; e++) { l[e] = expf(l[e] - mx); s += l[e]; }
        int i1 = 0; float p1 = -1.f;
#pragma unroll
        for (int e = 0; e < E; e++) { if (l[e] > p1) { p1 = l[e]; i1 = e; } }
        int i2 = -1; float p2 = -1.f;
#pragma unroll
        for (int e = 0; e < E; e++) { if (e != i1 && l[e] > p2) { p2 = l[e]; i2 = e; } }
        float inv = 1.f / s;
        int m0 = tok * 2;
        int pos = atomicAdd(&g_cnt[i1], 1);
        g_bm[i1*MAXM + pos] = m0;     g_bg[i1*MAXM + pos] = p1 * inv;
        pos = atomicAdd(&g_cnt[i2], 1);
        g_bm[i2*MAXM + pos] = m0 + 1; g_bg[i2*MAXM + pos] = p2 * inv;
    }
}

#define RCH 1024
__global__ void rank_kernel(int cap) {
    __shared__ float sg[RCH];
    __shared__ int   sm[RCH];
    int e = blockIdx.y;
    int cnt = g_cnt[e];
    if (blockIdx.x == 0 && threadIdx.x == 0) g_kept[e] = min(cnt, cap);
    int i = blockIdx.x * blockDim.x + threadIdx.x;
    bool has = (i < cnt);
    float gi = has ? g_bg[e*MAXM + i] : 0.f;
    int   mi = has ? g_bm[e*MAXM + i] : 0;
    int rank = 0;
    for (int j0 = 0; j0 < cnt; j0 += RCH) {
        int nj = min(RCH, cnt - j0);
        __syncthreads();
        for (int j = threadIdx.x; j < nj; j += blockDim.x) {
            sg[j] = g_bg[e*MAXM + j0 + j];
            sm[j] = g_bm[e*MAXM + j0 + j];
        }
        __syncthreads();
        if (has) {
            for (int j = 0; j < nj; j++) {
                float gj = sg[j]; int mj = sm[j];
                rank += (gj > gi) || (gj == gi && mj < mi);
            }
        }
    }
    if (has && rank < cap) {
        g_disp_tok[e*CAPP + rank] = mi >> 1;
        g_disp_g[e*CAPP + rank]   = gi;
    }
}

// weights fp32 -> fp16 (grid-stride over float4)
__global__ void wconv_kernel(const float* __restrict__ W, __half* __restrict__ out, int n4) {
    int i = blockIdx.x * blockDim.x + threadIdx.x;
    int stride = gridDim.x * blockDim.x;
    for (; i < n4; i += stride) {
        float4 v = __ldg(&((const float4*)W)[i]);
        uint32_t h0, h1;
        asm("cvt.rn.f16x2.f32 %0, %1, %2;" : "=r"(h0) : "f"(v.y), "f"(v.x));
        asm("cvt.rn.f16x2.f32 %0, %1, %2;" : "=r"(h1) : "f"(v.w), "f"(v.z));
        uint2 o; o.x = h0; o.y = h1;
        ((uint2*)out)[i] = o;
    }
}

// gather dispatched rows of x -> fp16 plane (zero-filled beyond kept)
__global__ void gather_kernel(const float* __restrict__ x) {
    int e = blockIdx.y;
    int warp = threadIdx.x >> 5, lane = threadIdx.x & 31;
    int r = blockIdx.x * 8 + warp;
    int kept = g_kept[e];
    bool v = r < kept;
    int tok = v ? g_disp_tok[e*CAPP + r] : 0;
    const float* src = x + (size_t)tok * DM;
    size_t dst = (size_t)(e*CAPP + r) * DM;
    for (int d = lane * 4; d < DM; d += 128) {
        float4 val = v ? __ldg((const float4*)(src + d)) : make_float4(0.f,0.f,0.f,0.f);
        uint32_t h0, h1;
        asm("cvt.rn.f16x2.f32 %0, %1, %2;" : "=r"(h0) : "f"(val.y), "f"(val.x));
        asm("cvt.rn.f16x2.f32 %0, %1, %2;" : "=r"(h1) : "f"(val.w), "f"(val.z));
        uint2 oh; oh.x = h0; oh.y = h1;
        *(uint2*)&g_xg[dst + d] = oh;
    }
}

// ---------------- GEMM (fp16 HMMA, cp.async 4-stage pipeline) ----------------
// IS2==0: A = g_xg [*,DM],  B = g_w1h [DM,HID], epi: silu(+b1) -> g_h
// IS2==1: A = g_h [*,HID],  B = g_w2h [HID,DM], epi: (+b2)*g -> atomicAdd Y
template <int KDIM, int NDIM, int IS2>
__global__ void __launch_bounds__(256, 1)
ffn_gemm_kernel(const __half* __restrict__ A, const __half* __restrict__ W,
                const float* __restrict__ Bias, float* __restrict__ Y) {
    extern __shared__ __align__(1024) char smem[];
    const uint32_t su = smem_u32(smem);
    const int tid = threadIdx.x, warp = tid >> 5, lane = tid & 31;
    const int e = blockIdx.z, m0 = blockIdx.y * BM, n0 = blockIdx.x * BN;
    const int kept = g_kept[e];

    int*   stok  = (int*)(smem + NSTAGE*STAGE);
    float* sgate = (float*)(smem + NSTAGE*STAGE + 512);
    if (tid < BM) {
        int r = m0 + tid; bool v = r < kept;
        stok[tid]  = v ? g_disp_tok[e*CAPP + r] : 0;
        sgate[tid] = v ? g_disp_g[e*CAPP + r]   : 0.f;
    }

    // warp tiling: 2 warps along M (64 rows), 4 along N (64 cols)
    const int wm = (warp >> 2) * 64;
    const int wn = (warp & 3) * 64;
    const int q = lane >> 3, rr = lane & 7;
    const int gp = lane >> 2, tg = lane & 3;

    const uint32_t a_base = (uint32_t)((wm + rr + (q & 1) * 8) * A_STRIDE + (q >> 1) * 16);
    const uint32_t b_base = (uint32_t)((rr + (q & 1) * 8) * B_STRIDE + (wn + (q >> 1) * 8) * 2);

    // producer (cp.async) mapping
    const int a_row = tid >> 2, a_kc = tid & 3;       // rows a_row, a_row+64; 16B chunk a_kc
    const int b_row = tid >> 5, b_nc = tid & 31;      // rows b_row + {0,8,16,24}
    const uint32_t a_cs = (uint32_t)(a_row * A_STRIDE + a_kc * 16);
    const uint32_t b_cs = (uint32_t)(b_row * B_STRIDE + b_nc * 16);
    const __half* At = A + (size_t)(e*CAPP + m0 + a_row)*KDIM + a_kc*8;
    const __half* Bt = W + (size_t)e*KDIM*NDIM + (size_t)b_row*NDIM + n0 + b_nc*8;

    float D[4][8][4];
#pragma unroll
    for (int a = 0; a < 4; a++)
#pragma unroll
        for (int b = 0; b < 8; b++)
#pragma unroll
            for (int c = 0; c < 4; c++) D[a][b][c] = 0.f;

    uint32_t Bh[8][2];
    const int KCH = KDIM / BK;

#define ISSUE(KT, SB) do {                                                     \
    const __half* _a = At + (size_t)(KT)*BK;                                   \
    CPA((SB) + OFF_A + a_cs, _a);                                              \
    CPA((SB) + OFF_A + a_cs + 64*A_STRIDE, _a + (size_t)64*KDIM);              \
    const __half* _b = Bt + (size_t)(KT)*BK*NDIM;                              \
    _Pragma("unroll")                                                          \
    for (int j = 0; j < 4; j++)                                                \
        CPA((SB) + OFF_B + b_cs + j*8*B_STRIDE, _b + (size_t)j*8*NDIM);        \
} while (0)

#define LDSMB(kk) do {                                                         \
    _Pragma("unroll")                                                          \
    for (int ntp = 0; ntp < 4; ntp++)                                          \
        LDSM4T(Bh[ntp*2][0],Bh[ntp*2][1],Bh[ntp*2+1][0],Bh[ntp*2+1][1],        \
               sb + OFF_B + b_base + (kk)*16*B_STRIDE + ntp*32);               \
} while (0)
#define MMA_MT(mt, kk) do {                                                    \
    uint32_t Ah0,Ah1,Ah2,Ah3;                                                  \
    LDSM4(Ah0,Ah1,Ah2,Ah3, sb + OFF_A + a_base + (mt)*16*A_STRIDE + (kk)*32);  \
    _Pragma("unroll")                                                          \
    for (int nt = 0; nt < 8; nt++)                                             \
        mma16816(D[mt][nt][0],D[mt][nt][1],D[mt][nt][2],D[mt][nt][3],          \
                 Ah0,Ah1,Ah2,Ah3, Bh[nt][0],Bh[nt][1]);                        \
} while (0)

    // prologue: 3 stages in flight
    ISSUE(0, su + 0*STAGE); CPA_COMMIT();
    ISSUE(1, su + 1*STAGE); CPA_COMMIT();
    ISSUE(2, su + 2*STAGE); CPA_COMMIT();

#pragma unroll 1
    for (int kt = 0; kt < KCH; kt++) {
        CPA_WAIT2();
        __syncthreads();
        const uint32_t sb = su + (uint32_t)(kt & (NSTAGE-1)) * STAGE;
        if (kt + 3 < KCH) ISSUE(kt + 3, su + (uint32_t)((kt + 3) & (NSTAGE-1)) * STAGE);
        CPA_COMMIT();
        LDSMB(0);
        MMA_MT(0,0); MMA_MT(1,0); MMA_MT(2,0); MMA_MT(3,0);
        LDSMB(1);
        MMA_MT(0,1); MMA_MT(1,1); MMA_MT(2,1); MMA_MT(3,1);
    }
#undef ISSUE
#undef LDSMB
#undef MMA_MT

    // ---------------- epilogue ----------------
#pragma unroll
    for (int mt = 0; mt < 4; mt++) {
#pragma unroll
        for (int nt = 0; nt < 8; nt++) {
            int lr = wm + mt*16 + gp;
            int c  = wn + nt*8 + 2*tg;
            int gn = n0 + c;
            float2 bb = *(const float2*)&Bias[(size_t)e*NDIM + gn];
#pragma unroll
            for (int half = 0; half < 2; half++) {
                int lrow = lr + half*8;
                int r = m0 + lrow;
                float v0 = D[mt][nt][half*2 + 0];
                float v1 = D[mt][nt][half*2 + 1];
                if (!IS2) {
                    if (r < kept) {
                        float o0 = silu_f(v0 + bb.x), o1 = silu_f(v1 + bb.y);
                        uint32_t hp;
                        asm("cvt.rn.f16x2.f32 %0, %1, %2;" : "=r"(hp) : "f"(o1), "f"(o0));
                        *(uint32_t*)&g_h[(size_t)(e*CAPP + r)*HID + gn] = hp;
                    }
                } else {
                    if (r < kept) {
                        int tok = stok[lrow];
                        float g = sgate[lrow];
                        atomicAdd(&Y[(size_t)tok*DM + gn    ], (v0 + bb.x) * g);
                        atomicAdd(&Y[(size_t)tok*DM + gn + 1], (v1 + bb.y) * g);
                    }
                }
            }
        }
    }
}

// ---------------- launch ----------------
extern "C" void kernel_launch(void* const* d_in, const int* in_sizes, int n_in,
                              void* d_out, int out_size) {
    const float* x  = (const float*)d_in[0];
    const float* Wr = (const float*)d_in[1];
    const float* br = (const float*)d_in[2];
    const float* W1 = (const float*)d_in[3];
    const float* b1 = (const float*)d_in[4];
    const float* W2 = (const float*)d_in[5];
    const float* b2 = (const float*)d_in[6];
    float* y = (float*)d_out;

    int N = in_sizes[0] / DM;
    if (N > MAXN) N = MAXN;
    int cap = (int)ceil(1.2 * (double)N / (double)E);
    if (cap > CAPP) cap = CAPP;
    int mt = (cap + BM - 1) / BM;

    cudaFuncSetAttribute(ffn_gemm_kernel<DM, HID, 0>,
                         cudaFuncAttributeMaxDynamicSharedMemorySize, SMEM_TOTAL);
    cudaFuncSetAttribute(ffn_gemm_kernel<HID, DM, 1>,
                         cudaFuncAttributeMaxDynamicSharedMemorySize, SMEM_TOTAL);

    cudaMemsetAsync(y, 0, (size_t)out_size * sizeof(float));
    zero_cnt_kernel<<<1, 32>>>();

    // weight conversion (independent of routing)
    __half* w1h; cudaGetSymbolAddress((void**)&w1h, g_w1h);
    __half* w2h; cudaGetSymbolAddress((void**)&w2h, g_w2h);
    const int n4 = (E*DM*HID) / 4;
    wconv_kernel<<<4096, 256>>>(W1, w1h, n4);
    wconv_kernel<<<4096, 256>>>(W2, w2h, n4);

    router_kernel<<<(N + 7) / 8, 256>>>(x, Wr, br, N);
    dim3 rg((2 * N + 255) / 256, E);
    rank_kernel<<<rg, 256>>>(cap);

    dim3 gg(CAPP / 8, E);
    gather_kernel<<<gg, 256>>>(x);

    __half* xgh; cudaGetSymbolAddress((void**)&xgh, g_xg);
    __half* hh;  cudaGetSymbolAddress((void**)&hh,  g_h);

    dim3 g1(HID / BN, mt, E);
    ffn_gemm_kernel<DM, HID, 0><<<g1, 256, SMEM_TOTAL>>>(xgh, w1h, b1, y);

    dim3 g2(DM / BN, mt, E);
    ffn_gemm_kernel<HID, DM, 1><<<g2, 256, SMEM_TOTAL>>>(hh, w2h, b2, y);
}